// round 7
// baseline (speedup 1.0000x reference)
#include <cuda_runtime.h>
#include <cuda_bf16.h>
#include <cstdint>

#define V_TOTAL 267735
#define NROWS   512
#define YSTRIDE 1360   // 1024 + 256 + 64 + 16

// ---------------- device scratch (no allocations allowed) ----------------
__device__ float          g_Yf[NROWS * YSTRIDE];     // fp32 projections
__device__ __nv_bfloat16  g_Yh[NROWS * YSTRIDE];     // bf16 projections
__device__ float          g_rowsum[4 * NROWS];       // sum(exp(logit)) per region/row
__device__ float          g_SUB[4 * NROWS];          // per-region per-row subtract term

// ---------------- K0: zero the row sums ----------------
__global__ void k_zero() {
    int i = blockIdx.x * blockDim.x + threadIdx.x;
    if (i < 4 * NROWS) g_rowsum[i] = 0.f;
}

// ---------------- K1: projections  Y = H(512x1024) @ P^T (E x 1024), fp32 ----
__global__ void k_proj(const float* __restrict__ H, const float* __restrict__ P,
                       int E, int yofs) {
    __shared__ float As[16][66];
    __shared__ float Bs[16][66];
    const int tid = threadIdx.x;
    const int tx = tid & 15, ty = tid >> 4;
    const int m0 = blockIdx.y * 64, n0 = blockIdx.x * 64;

    float acc[4][4];
#pragma unroll
    for (int i = 0; i < 4; i++)
#pragma unroll
        for (int j = 0; j < 4; j++) acc[i][j] = 0.f;

    for (int k0 = 0; k0 < 1024; k0 += 16) {
#pragma unroll
        for (int i = 0; i < 4; i++) {
            int e = tid + i * 256;
            int r = e >> 4, c = e & 15;
            As[c][r] = H[(size_t)(m0 + r) * 1024 + k0 + c];
            int nn = n0 + r;
            Bs[c][r] = (nn < E) ? P[(size_t)nn * 1024 + k0 + c] : 0.f;
        }
        __syncthreads();
#pragma unroll
        for (int k = 0; k < 16; k++) {
            float am[4], bn[4];
#pragma unroll
            for (int i = 0; i < 4; i++) am[i] = As[k][ty * 4 + i];
#pragma unroll
            for (int j = 0; j < 4; j++) bn[j] = Bs[k][tx * 4 + j];
#pragma unroll
            for (int i = 0; i < 4; i++)
#pragma unroll
                for (int j = 0; j < 4; j++) acc[i][j] += am[i] * bn[j];
        }
        __syncthreads();
    }
#pragma unroll
    for (int i = 0; i < 4; i++) {
        int m = m0 + ty * 4 + i;
#pragma unroll
        for (int j = 0; j < 4; j++) {
            int n = n0 + tx * 4 + j;
            if (n < E) {
                size_t idx = (size_t)m * YSTRIDE + yofs + n;
                g_Yf[idx] = acc[i][j];
                g_Yh[idx] = __float2bfloat16(acc[i][j]);
            }
        }
    }
}

// ---------------- K2: logits GEMM (bf16 mma) + fused exp-sum ----------------
// block tile: 64 rows x 128 cols, 8 warps (2 along M x 4 along N), warp 32x32.
// A (y, bf16) staged once in smem (full K). B fragments loaded directly from
// global fp32 W and converted in registers.
__global__ void k_logits(const float* __restrict__ W, const float* __restrict__ b,
                         float* __restrict__ out,
                         int N, int K, int yofs, int colBase, int region) {
    extern __shared__ char smem_raw[];
    __nv_bfloat16* As = (__nv_bfloat16*)smem_raw;
    const int LDA = K + 8;

    const int tid  = threadIdx.x;
    const int lane = tid & 31, wid = tid >> 5;
    const int mBlk = blockIdx.x * 64;
    const int nBlk = blockIdx.y * 128;

    // ---- stage A tile (64 x K bf16), 16B chunks, conflict-safe layout ----
    {
        const int cpr = K >> 3;  // uint4 chunks per row
        for (int r = wid * 8; r < wid * 8 + 8; r++) {
            const uint4* src = (const uint4*)(g_Yh + (size_t)(mBlk + r) * YSTRIDE + yofs);
            uint4* dst = (uint4*)(As + r * LDA);
            for (int c = lane; c < cpr; c += 32) dst[c] = src[c];
        }
    }
    __syncthreads();

    const int wm  = wid & 1;      // 0..1 (M)
    const int wn  = wid >> 1;     // 0..3 (N)
    const int qr  = lane >> 2;    // 0..7
    const int qc2 = (lane & 3) * 2;

    float acc[2][4][4];
#pragma unroll
    for (int mt = 0; mt < 2; mt++)
#pragma unroll
        for (int nt = 0; nt < 4; nt++)
#pragma unroll
            for (int c = 0; c < 4; c++) acc[mt][nt][c] = 0.f;

    int  nIdx[4];
    bool nValid[4];
#pragma unroll
    for (int nt = 0; nt < 4; nt++) {
        nIdx[nt]   = nBlk + wn * 32 + nt * 8 + qr;
        nValid[nt] = nIdx[nt] < N;
    }

    const int NK = K >> 4;
    float2 fB[4][2];
#pragma unroll
    for (int nt = 0; nt < 4; nt++) {
        if (nValid[nt]) {
            const float* wp = W + (size_t)nIdx[nt] * K + qc2;
            fB[nt][0] = *(const float2*)(wp);
            fB[nt][1] = *(const float2*)(wp + 8);
        } else {
            fB[nt][0] = make_float2(0.f, 0.f);
            fB[nt][1] = make_float2(0.f, 0.f);
        }
    }

    for (int ks = 0; ks < NK; ks++) {
        const int k0 = ks * 16;
        float2 nxt[4][2];
        if (ks + 1 < NK) {
#pragma unroll
            for (int nt = 0; nt < 4; nt++) {
                if (nValid[nt]) {
                    const float* wp = W + (size_t)nIdx[nt] * K + k0 + 16 + qc2;
                    nxt[nt][0] = *(const float2*)(wp);
                    nxt[nt][1] = *(const float2*)(wp + 8);
                } else {
                    nxt[nt][0] = make_float2(0.f, 0.f);
                    nxt[nt][1] = make_float2(0.f, 0.f);
                }
            }
        }

        uint32_t a[2][4];
#pragma unroll
        for (int mt = 0; mt < 2; mt++) {
            const __nv_bfloat16* ap = As + (wm * 32 + mt * 16 + qr) * LDA + k0 + qc2;
            a[mt][0] = *(const uint32_t*)(ap);
            a[mt][1] = *(const uint32_t*)(ap + 8 * LDA);
            a[mt][2] = *(const uint32_t*)(ap + 8);
            a[mt][3] = *(const uint32_t*)(ap + 8 * LDA + 8);
        }

        uint32_t bfr[4][2];
#pragma unroll
        for (int nt = 0; nt < 4; nt++)
#pragma unroll
            for (int h = 0; h < 2; h++) {
                __nv_bfloat162 hv = __floats2bfloat162_rn(fB[nt][h].x, fB[nt][h].y);
                bfr[nt][h] = *reinterpret_cast<uint32_t*>(&hv);
            }

#pragma unroll
        for (int mt = 0; mt < 2; mt++)
#pragma unroll
            for (int nt = 0; nt < 4; nt++) {
                asm volatile(
                    "mma.sync.aligned.m16n8k16.row.col.f32.bf16.bf16.f32 "
                    "{%0,%1,%2,%3}, {%4,%5,%6,%7}, {%8,%9}, {%0,%1,%2,%3};\n"
                    : "+f"(acc[mt][nt][0]), "+f"(acc[mt][nt][1]),
                      "+f"(acc[mt][nt][2]), "+f"(acc[mt][nt][3])
                    : "r"(a[mt][0]), "r"(a[mt][1]), "r"(a[mt][2]), "r"(a[mt][3]),
                      "r"(bfr[nt][0]), "r"(bfr[nt][1]));
            }

        if (ks + 1 < NK) {
#pragma unroll
            for (int nt = 0; nt < 4; nt++) {
                fB[nt][0] = nxt[nt][0];
                fB[nt][1] = nxt[nt][1];
            }
        }
    }

    // ---- epilogue: store logits + per-row exp-sums ----
    __syncthreads();
    float* srow = (float*)smem_raw;  // reuse smem: 64 per-row partial sums
    if (tid < 64) srow[tid] = 0.f;
    __syncthreads();

#pragma unroll
    for (int mt = 0; mt < 2; mt++) {
#pragma unroll
        for (int hh = 0; hh < 2; hh++) {
            int rloc = wm * 32 + mt * 16 + qr + hh * 8;
            size_t rgl = (size_t)(mBlk + rloc);
            float part = 0.f;
#pragma unroll
            for (int nt = 0; nt < 4; nt++) {
                int n0 = nBlk + wn * 32 + nt * 8 + qc2;
#pragma unroll
                for (int p = 0; p < 2; p++) {
                    int n = n0 + p;
                    if (n < N) {
                        float v = acc[mt][nt][hh * 2 + p] + b[n];
                        out[rgl * V_TOTAL + colBase + n] = v;
                        part += __expf(v);
                    }
                }
            }
            // lanes sharing a row differ only in (lane & 3)
            part += __shfl_xor_sync(0xffffffffu, part, 1);
            part += __shfl_xor_sync(0xffffffffu, part, 2);
            if ((lane & 3) == 0) atomicAdd(&srow[rloc], part);
        }
    }
    __syncthreads();
    if (tid < 64)
        atomicAdd(&g_rowsum[region * NROWS + mBlk + tid], srow[tid]);
}

// ---------------- K3: cluster logits + per-region subtract terms ----------------
__global__ void k_head_fix(const float* __restrict__ cw, const float* __restrict__ cb) {
    const int row = blockIdx.x;
    const int tid = threadIdx.x;  // 128
    __shared__ float red[3][128];
    float p0 = 0.f, p1 = 0.f, p2 = 0.f;
    const float* y = g_Yf + (size_t)row * YSTRIDE;  // y0, K=1024
    for (int e = tid; e < 1024; e += 128) {
        float yv = y[e];
        p0 += yv * cw[e];
        p1 += yv * cw[1024 + e];
        p2 += yv * cw[2048 + e];
    }
    red[0][tid] = p0; red[1][tid] = p1; red[2][tid] = p2;
    __syncthreads();
    for (int s = 64; s > 0; s >>= 1) {
        if (tid < s) {
            red[0][tid] += red[0][tid + s];
            red[1][tid] += red[1][tid + s];
            red[2][tid] += red[2][tid + s];
        }
        __syncthreads();
    }
    if (tid == 0) {
        float c0 = red[0][0] + cb[0];
        float c1 = red[1][0] + cb[1];
        float c2 = red[2][0] + cb[2];
        float s = g_rowsum[row] + __expf(c0) + __expf(c1) + __expf(c2);
        float lse0 = logf(s);
        g_SUB[row] = lse0;                       // head: out = logit - lse0
        float cl[3] = {c0 - lse0, c1 - lse0, c2 - lse0};
        for (int i = 1; i < 4; i++)              // tail: out = logit - lse_i + cl[i-1]
            g_SUB[i * NROWS + row] = logf(g_rowsum[i * NROWS + row]) - cl[i - 1];
    }
}

// ---------------- K4: vectorized subtract over the whole output ----------------
__global__ void k_sub(float* __restrict__ out, unsigned int total4) {
    unsigned int i4 = blockIdx.x * blockDim.x + threadIdx.x;
    if (i4 >= total4) return;
    unsigned int e = i4 * 4u;
    unsigned int row = e / (unsigned)V_TOTAL;
    unsigned int col = e - row * (unsigned)V_TOTAL;
    float4 v = *((const float4*)out + i4);
    float vv[4] = {v.x, v.y, v.z, v.w};
#pragma unroll
    for (int j = 0; j < 4; j++) {
        if (col >= (unsigned)V_TOTAL) { col -= (unsigned)V_TOTAL; row++; }
        int reg = (col < 20000u) ? 0 : (col < 40000u) ? 1 : (col < 200000u) ? 2 : 3;
        vv[j] -= g_SUB[reg * NROWS + row];
        col++;
    }
    v.x = vv[0]; v.y = vv[1]; v.z = vv[2]; v.w = vv[3];
    *((float4*)out + i4) = v;
}

// ---------------- K5: loss = mean(-lp[target]) ----------------
__global__ void k_loss(const float* __restrict__ out, const int* __restrict__ tgt,
                       float* __restrict__ loss_out) {
    __shared__ float red[512];
    int r = threadIdx.x;
    int t = tgt[r];
    red[r] = -out[(size_t)r * V_TOTAL + t];
    __syncthreads();
    for (int s = 256; s > 0; s >>= 1) {
        if (r < s) red[r] += red[r + s];
        __syncthreads();
    }
    if (r == 0) *loss_out = red[0] / 512.f;
}

// ---------------- launch ----------------
extern "C" void kernel_launch(void* const* d_in, const int* in_sizes, int n_in,
                              void* d_out, int out_size) {
    const float* hidden = (const float*)d_in[0];
    const int*   target = (const int*)d_in[1];
    const float* cw     = (const float*)d_in[2];
    const float* cb     = (const float*)d_in[3];
    const float* W[4]  = {(const float*)d_in[4],  (const float*)d_in[7],
                          (const float*)d_in[10], (const float*)d_in[13]};
    const float* bb[4] = {(const float*)d_in[5],  (const float*)d_in[8],
                          (const float*)d_in[11], (const float*)d_in[14]};
    const float* P[4]  = {(const float*)d_in[6],  (const float*)d_in[9],
                          (const float*)d_in[12], (const float*)d_in[15]};
    float* out = (float*)d_out;

    static const int Ns[4]      = {20000, 20000, 160000, 67735};
    static const int Ks[4]      = {1024, 256, 64, 16};
    static const int yofs[4]    = {0, 1024, 1280, 1344};
    static const int colBase[4] = {0, 20000, 40000, 200000};

    cudaFuncSetAttribute(k_logits, cudaFuncAttributeMaxDynamicSharedMemorySize,
                         64 * (1024 + 8) * 2);

    k_zero<<<8, 256>>>();

    for (int i = 0; i < 4; i++)
        k_proj<<<dim3((Ks[i] + 63) / 64, 8), 256>>>(hidden, P[i], Ks[i], yofs[i]);

    for (int i = 0; i < 4; i++) {
        dim3 grid(8, (Ns[i] + 127) / 128);   // mtile fast-varying -> W reuse in L2
        int smem = 64 * (Ks[i] + 8) * 2;
        k_logits<<<grid, 256, smem>>>(W[i], bb[i], out, Ns[i], Ks[i],
                                      yofs[i], colBase[i], i);
    }

    k_head_fix<<<512, 128>>>(cw, cb);

    unsigned int total4 = (unsigned int)NROWS * (unsigned int)V_TOTAL / 4u;
    k_sub<<<(total4 + 255u) / 256u, 256>>>(out, total4);

    k_loss<<<1, 512>>>(out, target, out + (size_t)out_size - 1);
}

// round 8
// speedup vs baseline: 1.0075x; 1.0075x over previous
#include <cuda_runtime.h>
#include <cuda_bf16.h>
#include <cstdint>

#define V_TOTAL 267735
#define NROWS   512
#define YSTRIDE 1360   // 1024 + 256 + 64 + 16

// ---------------- device scratch (no allocations allowed) ----------------
__device__ float          g_Yf[NROWS * YSTRIDE];     // fp32 projections
__device__ __nv_bfloat16  g_Yh[NROWS * YSTRIDE];     // bf16 projections
__device__ float          g_rowsum[4 * NROWS];       // sum(exp(logit)) per region/row
__device__ float          g_SUB[4 * NROWS];          // per-region per-row subtract term

// ---------------- K0: zero the row sums ----------------
__global__ void k_zero() {
    int i = blockIdx.x * blockDim.x + threadIdx.x;
    if (i < 4 * NROWS) g_rowsum[i] = 0.f;
}

// ---------------- K1: projections  Y = H(512x1024) @ P^T (E x 1024), fp32 ----
__global__ void k_proj(const float* __restrict__ H, const float* __restrict__ P,
                       int E, int yofs) {
    __shared__ float As[16][66];
    __shared__ float Bs[16][66];
    const int tid = threadIdx.x;
    const int tx = tid & 15, ty = tid >> 4;
    const int m0 = blockIdx.y * 64, n0 = blockIdx.x * 64;

    float acc[4][4];
#pragma unroll
    for (int i = 0; i < 4; i++)
#pragma unroll
        for (int j = 0; j < 4; j++) acc[i][j] = 0.f;

    for (int k0 = 0; k0 < 1024; k0 += 16) {
#pragma unroll
        for (int i = 0; i < 4; i++) {
            int e = tid + i * 256;
            int r = e >> 4, c = e & 15;
            As[c][r] = H[(size_t)(m0 + r) * 1024 + k0 + c];
            int nn = n0 + r;
            Bs[c][r] = (nn < E) ? P[(size_t)nn * 1024 + k0 + c] : 0.f;
        }
        __syncthreads();
#pragma unroll
        for (int k = 0; k < 16; k++) {
            float am[4], bn[4];
#pragma unroll
            for (int i = 0; i < 4; i++) am[i] = As[k][ty * 4 + i];
#pragma unroll
            for (int j = 0; j < 4; j++) bn[j] = Bs[k][tx * 4 + j];
#pragma unroll
            for (int i = 0; i < 4; i++)
#pragma unroll
                for (int j = 0; j < 4; j++) acc[i][j] += am[i] * bn[j];
        }
        __syncthreads();
    }
#pragma unroll
    for (int i = 0; i < 4; i++) {
        int m = m0 + ty * 4 + i;
#pragma unroll
        for (int j = 0; j < 4; j++) {
            int n = n0 + tx * 4 + j;
            if (n < E) {
                size_t idx = (size_t)m * YSTRIDE + yofs + n;
                g_Yf[idx] = acc[i][j];
                g_Yh[idx] = __float2bfloat16(acc[i][j]);
            }
        }
    }
}

// ---------------- K2: logits GEMM (bf16 mma) + fused exp-sum ----------------
// block tile: 64 rows x 128 cols, 8 warps (2 along M x 4 along N), warp 32x32.
// A (y, bf16) staged once in smem (full K). B fragments loaded directly from
// global fp32 W and converted in registers.
__global__ void k_logits(const float* __restrict__ W, const float* __restrict__ b,
                         float* __restrict__ out,
                         int N, int K, int yofs, int colBase, int region) {
    extern __shared__ char smem_raw[];
    __nv_bfloat16* As = (__nv_bfloat16*)smem_raw;
    const int LDA = K + 8;

    const int tid  = threadIdx.x;
    const int lane = tid & 31, wid = tid >> 5;
    const int mBlk = blockIdx.x * 64;
    const int nBlk = blockIdx.y * 128;

    // ---- stage A tile (64 x K bf16), 16B chunks, conflict-safe layout ----
    {
        const int cpr = K >> 3;  // uint4 chunks per row
        for (int r = wid * 8; r < wid * 8 + 8; r++) {
            const uint4* src = (const uint4*)(g_Yh + (size_t)(mBlk + r) * YSTRIDE + yofs);
            uint4* dst = (uint4*)(As + r * LDA);
            for (int c = lane; c < cpr; c += 32) dst[c] = src[c];
        }
    }
    __syncthreads();

    const int wm  = wid & 1;      // 0..1 (M)
    const int wn  = wid >> 1;     // 0..3 (N)
    const int qr  = lane >> 2;    // 0..7
    const int qc2 = (lane & 3) * 2;

    float acc[2][4][4];
#pragma unroll
    for (int mt = 0; mt < 2; mt++)
#pragma unroll
        for (int nt = 0; nt < 4; nt++)
#pragma unroll
            for (int c = 0; c < 4; c++) acc[mt][nt][c] = 0.f;

    int  nIdx[4];
    bool nValid[4];
#pragma unroll
    for (int nt = 0; nt < 4; nt++) {
        nIdx[nt]   = nBlk + wn * 32 + nt * 8 + qr;
        nValid[nt] = nIdx[nt] < N;
    }

    const int NK = K >> 4;
    float2 fB[4][2];
#pragma unroll
    for (int nt = 0; nt < 4; nt++) {
        if (nValid[nt]) {
            const float* wp = W + (size_t)nIdx[nt] * K + qc2;
            fB[nt][0] = *(const float2*)(wp);
            fB[nt][1] = *(const float2*)(wp + 8);
        } else {
            fB[nt][0] = make_float2(0.f, 0.f);
            fB[nt][1] = make_float2(0.f, 0.f);
        }
    }

    for (int ks = 0; ks < NK; ks++) {
        const int k0 = ks * 16;
        float2 nxt[4][2];
        if (ks + 1 < NK) {
#pragma unroll
            for (int nt = 0; nt < 4; nt++) {
                if (nValid[nt]) {
                    const float* wp = W + (size_t)nIdx[nt] * K + k0 + 16 + qc2;
                    nxt[nt][0] = *(const float2*)(wp);
                    nxt[nt][1] = *(const float2*)(wp + 8);
                } else {
                    nxt[nt][0] = make_float2(0.f, 0.f);
                    nxt[nt][1] = make_float2(0.f, 0.f);
                }
            }
        }

        uint32_t a[2][4];
#pragma unroll
        for (int mt = 0; mt < 2; mt++) {
            const __nv_bfloat16* ap = As + (wm * 32 + mt * 16 + qr) * LDA + k0 + qc2;
            a[mt][0] = *(const uint32_t*)(ap);
            a[mt][1] = *(const uint32_t*)(ap + 8 * LDA);
            a[mt][2] = *(const uint32_t*)(ap + 8);
            a[mt][3] = *(const uint32_t*)(ap + 8 * LDA + 8);
        }

        uint32_t bfr[4][2];
#pragma unroll
        for (int nt = 0; nt < 4; nt++)
#pragma unroll
            for (int h = 0; h < 2; h++) {
                __nv_bfloat162 hv = __floats2bfloat162_rn(fB[nt][h].x, fB[nt][h].y);
                bfr[nt][h] = *reinterpret_cast<uint32_t*>(&hv);
            }

#pragma unroll
        for (int mt = 0; mt < 2; mt++)
#pragma unroll
            for (int nt = 0; nt < 4; nt++) {
                asm volatile(
                    "mma.sync.aligned.m16n8k16.row.col.f32.bf16.bf16.f32 "
                    "{%0,%1,%2,%3}, {%4,%5,%6,%7}, {%8,%9}, {%0,%1,%2,%3};\n"
                    : "+f"(acc[mt][nt][0]), "+f"(acc[mt][nt][1]),
                      "+f"(acc[mt][nt][2]), "+f"(acc[mt][nt][3])
                    : "r"(a[mt][0]), "r"(a[mt][1]), "r"(a[mt][2]), "r"(a[mt][3]),
                      "r"(bfr[nt][0]), "r"(bfr[nt][1]));
            }

        if (ks + 1 < NK) {
#pragma unroll
            for (int nt = 0; nt < 4; nt++) {
                fB[nt][0] = nxt[nt][0];
                fB[nt][1] = nxt[nt][1];
            }
        }
    }

    // ---- epilogue: store logits + per-row exp-sums ----
    __syncthreads();
    float* srow = (float*)smem_raw;  // reuse smem: 64 per-row partial sums
    if (tid < 64) srow[tid] = 0.f;
    __syncthreads();

#pragma unroll
    for (int mt = 0; mt < 2; mt++) {
#pragma unroll
        for (int hh = 0; hh < 2; hh++) {
            int rloc = wm * 32 + mt * 16 + qr + hh * 8;
            size_t rgl = (size_t)(mBlk + rloc);
            float part = 0.f;
#pragma unroll
            for (int nt = 0; nt < 4; nt++) {
                int n0 = nBlk + wn * 32 + nt * 8 + qc2;
#pragma unroll
                for (int p = 0; p < 2; p++) {
                    int n = n0 + p;
                    if (n < N) {
                        float v = acc[mt][nt][hh * 2 + p] + b[n];
                        out[rgl * V_TOTAL + colBase + n] = v;
                        part += __expf(v);
                    }
                }
            }
            // lanes sharing a row differ only in (lane & 3)
            part += __shfl_xor_sync(0xffffffffu, part, 1);
            part += __shfl_xor_sync(0xffffffffu, part, 2);
            if ((lane & 3) == 0) atomicAdd(&srow[rloc], part);
        }
    }
    __syncthreads();
    if (tid < 64)
        atomicAdd(&g_rowsum[region * NROWS + mBlk + tid], srow[tid]);
}

// ---------------- K3: cluster logits + per-region subtract terms ----------------
__global__ void k_head_fix(const float* __restrict__ cw, const float* __restrict__ cb) {
    const int row = blockIdx.x;
    const int tid = threadIdx.x;  // 128
    __shared__ float red[3][128];
    float p0 = 0.f, p1 = 0.f, p2 = 0.f;
    const float* y = g_Yf + (size_t)row * YSTRIDE;  // y0, K=1024
    for (int e = tid; e < 1024; e += 128) {
        float yv = y[e];
        p0 += yv * cw[e];
        p1 += yv * cw[1024 + e];
        p2 += yv * cw[2048 + e];
    }
    red[0][tid] = p0; red[1][tid] = p1; red[2][tid] = p2;
    __syncthreads();
    for (int s = 64; s > 0; s >>= 1) {
        if (tid < s) {
            red[0][tid] += red[0][tid + s];
            red[1][tid] += red[1][tid + s];
            red[2][tid] += red[2][tid + s];
        }
        __syncthreads();
    }
    if (tid == 0) {
        float c0 = red[0][0] + cb[0];
        float c1 = red[1][0] + cb[1];
        float c2 = red[2][0] + cb[2];
        float s = g_rowsum[row] + __expf(c0) + __expf(c1) + __expf(c2);
        float lse0 = logf(s);
        g_SUB[row] = lse0;                       // head: out = logit - lse0
        float cl[3] = {c0 - lse0, c1 - lse0, c2 - lse0};
        for (int i = 1; i < 4; i++)              // tail: out = logit - lse_i + cl[i-1]
            g_SUB[i * NROWS + row] = logf(g_rowsum[i * NROWS + row]) - cl[i - 1];
    }
}

// ---------------- K4: vectorized subtract over the whole output ----------------
__global__ void k_sub(float* __restrict__ out, unsigned int total4) {
    unsigned int i4 = blockIdx.x * blockDim.x + threadIdx.x;
    if (i4 >= total4) return;
    unsigned int e = i4 * 4u;
    unsigned int row = e / (unsigned)V_TOTAL;
    unsigned int col = e - row * (unsigned)V_TOTAL;
    float4 v = *((const float4*)out + i4);
    float vv[4] = {v.x, v.y, v.z, v.w};
#pragma unroll
    for (int j = 0; j < 4; j++) {
        if (col >= (unsigned)V_TOTAL) { col -= (unsigned)V_TOTAL; row++; }
        int reg = (col < 20000u) ? 0 : (col < 40000u) ? 1 : (col < 200000u) ? 2 : 3;
        vv[j] -= g_SUB[reg * NROWS + row];
        col++;
    }
    v.x = vv[0]; v.y = vv[1]; v.z = vv[2]; v.w = vv[3];
    *((float4*)out + i4) = v;
}

// ---------------- K5: loss = mean(-lp[target]) ----------------
__global__ void k_loss(const float* __restrict__ out, const int* __restrict__ tgt,
                       float* __restrict__ loss_out) {
    __shared__ float red[512];
    int r = threadIdx.x;
    int t = tgt[r];
    red[r] = -out[(size_t)r * V_TOTAL + t];
    __syncthreads();
    for (int s = 256; s > 0; s >>= 1) {
        if (r < s) red[r] += red[r + s];
        __syncthreads();
    }
    if (r == 0) *loss_out = red[0] / 512.f;
}

// ---------------- launch ----------------
extern "C" void kernel_launch(void* const* d_in, const int* in_sizes, int n_in,
                              void* d_out, int out_size) {
    const float* hidden = (const float*)d_in[0];
    const int*   target = (const int*)d_in[1];
    const float* cw     = (const float*)d_in[2];
    const float* cb     = (const float*)d_in[3];
    const float* W[4]  = {(const float*)d_in[4],  (const float*)d_in[7],
                          (const float*)d_in[10], (const float*)d_in[13]};
    const float* bb[4] = {(const float*)d_in[5],  (const float*)d_in[8],
                          (const float*)d_in[11], (const float*)d_in[14]};
    const float* P[4]  = {(const float*)d_in[6],  (const float*)d_in[9],
                          (const float*)d_in[12], (const float*)d_in[15]};
    float* out = (float*)d_out;

    static const int Ns[4]      = {20000, 20000, 160000, 67735};
    static const int Ks[4]      = {1024, 256, 64, 16};
    static const int yofs[4]    = {0, 1024, 1280, 1344};
    static const int colBase[4] = {0, 20000, 40000, 200000};

    cudaFuncSetAttribute(k_logits, cudaFuncAttributeMaxDynamicSharedMemorySize,
                         64 * (1024 + 8) * 2);

    k_zero<<<8, 256>>>();

    for (int i = 0; i < 4; i++)
        k_proj<<<dim3((Ks[i] + 63) / 64, 8), 256>>>(hidden, P[i], Ks[i], yofs[i]);

    for (int i = 0; i < 4; i++) {
        dim3 grid(8, (Ns[i] + 127) / 128);   // mtile fast-varying -> W reuse in L2
        int smem = 64 * (Ks[i] + 8) * 2;
        k_logits<<<grid, 256, smem>>>(W[i], bb[i], out, Ns[i], Ks[i],
                                      yofs[i], colBase[i], i);
    }

    k_head_fix<<<512, 128>>>(cw, cb);

    unsigned int total4 = (unsigned int)NROWS * (unsigned int)V_TOTAL / 4u;
    k_sub<<<(total4 + 255u) / 256u, 256>>>(out, total4);

    k_loss<<<1, 512>>>(out, target, out + (size_t)out_size - 1);
}